// round 15
// baseline (speedup 1.0000x reference)
#include <cuda_runtime.h>
#include <math.h>

#define BB 16
#define TT 32

__constant__ float c_anch[18] = {
    10.f/8.f, 13.f/8.f, 16.f/8.f, 30.f/8.f, 33.f/8.f, 23.f/8.f,
    30.f/16.f, 61.f/16.f, 62.f/16.f, 45.f/16.f, 59.f/16.f, 119.f/16.f,
    116.f/32.f, 90.f/32.f, 156.f/32.f, 198.f/32.f, 373.f/32.f, 326.f/32.f
};

// Dense geometry (runs of 5 contiguous channels per (b,anchor), run = b*3+a).
// 256-thread blocks, 8 front-batched float4 loads per thread (2048 f4/block)
// — the measured MLP optimum (delivery GB/s: 2->843, 4->927, 8->1011, 16->972):
//   scale0: 48 runs x 8000 f4, 4 blocks/run -> dense idx [0,192)
//   scale1: 48 runs x 2000 f4, 1 block/run  -> dense idx [192,240)
//   scale2: 48 runs x  500 f4, 4 runs/block -> dense idx [240,252)
// Corr: 48 DEDICATED blocks [252,300) — dispatched AFTER the dense stream
// (measured faster than corr-first). One (scale,batch) unit each,
// 8 warps x 4 targets, warp-local register prep + shuffle gather.
#define NDB 252
#define NCB 48
#define NBLK (NDB + NCB)   // 300 blocks x 256 threads

// accumulators per scale: [0]=box_base [1]=sp_base [2]=box_delta
//                         [3]=obj_sum [4]=noobj_sub [5]=cls_sum [6]=n_obj
// zero at init; reset by the last block of every replay.
__device__ float g_acc[3][7];
__device__ int   g_ticket;

__device__ __forceinline__ float sp(float x) {
    // softplus = max(x,0) + log1p(exp(-|x|)); 2-MUFU form
    const float z = exp2f(-1.44269504f * fabsf(x));
    return fmaxf(x, 0.f) + 0.69314718f * __log2f(1.f + z);
}

__device__ __forceinline__ float warp_sum(float v) {
    #pragma unroll
    for (int o = 16; o; o >>= 1) v += __shfl_down_sync(0xffffffffu, v, o);
    return v;
}

__global__ void __launch_bounds__(256)
fused_kernel(const float* __restrict__ p0,
             const float* __restrict__ p1,
             const float* __restrict__ p2,
             const float* __restrict__ targets,
             float* __restrict__ out) {
    const int bid = blockIdx.x, tid = threadIdx.x;
    const int lane = tid & 31, w = tid >> 5;
    const unsigned FULL = 0xffffffffu;

    __shared__ float red[8][2];

    if (bid < NDB) {
        // ================= dense block: 8 front-batched LDG.128 =============
        float4 v[8];
        bool isbox[8];
        const float4 z4 = make_float4(0.f, 0.f, 0.f, 0.f);
        int dsc;

        if (bid < 192) {
            dsc = 0;
            const int run = bid >> 2, q = bid & 3;
            const float4* b4 = reinterpret_cast<const float4*>(p0) + run * 40000;
            const int f0 = q * 2048;
            #pragma unroll
            for (int k = 0; k < 8; k++) {
                const int i = f0 + k * 256 + tid;
                const bool ok = i < 8000;
                v[k] = ok ? b4[i] : z4;
                isbox[k] = (!ok) || (i < 6400);
            }
        } else if (bid < 240) {
            dsc = 1;
            const int run = bid - 192;
            const float4* b4 = reinterpret_cast<const float4*>(p1) + run * 10000;
            #pragma unroll
            for (int k = 0; k < 8; k++) {
                const int i = k * 256 + tid;
                const bool ok = i < 2000;
                v[k] = ok ? b4[i] : z4;
                isbox[k] = (!ok) || (i < 1600);
            }
        } else {
            dsc = 2;
            const int j = bid - 240;                   // 4 runs per block
            const float4* b4 = reinterpret_cast<const float4*>(p2) + j * 10000;
            #pragma unroll
            for (int k = 0; k < 8; k++) {
                const int i = k * 256 + tid;
                const bool ok = i < 2000;
                const int r = i / 500;                 // constant divisor
                const int off = i - 500 * r;
                v[k] = ok ? b4[r * 2500 + off] : z4;
                isbox[k] = (!ok) || (off < 400);
            }
        }

        float bacc = 0.f, sacc = 0.f;
        #pragma unroll
        for (int k = 0; k < 8; k++) {
            if (isbox[k]) {
                bacc += v[k].x * v[k].x + v[k].y * v[k].y
                      + v[k].z * v[k].z + v[k].w * v[k].w;
            } else {
                sacc += sp(v[k].x) + sp(v[k].y) + sp(v[k].z) + sp(v[k].w);
            }
        }
        bacc = warp_sum(bacc); sacc = warp_sum(sacc);
        if (lane == 0) { red[w][0] = bacc; red[w][1] = sacc; }
        __syncthreads();
        if (tid == 0) {
            float b2 = 0.f, s2 = 0.f;
            #pragma unroll
            for (int i = 0; i < 8; i++) { b2 += red[i][0]; s2 += red[i][1]; }
            atomicAdd(&g_acc[dsc][0], b2);
            atomicAdd(&g_acc[dsc][1], s2);
        }
    } else {
        // ================= dedicated corr block (no dense work) =============
        const int unit = bid - NDB;     // 0..47
        const int s   = unit >> 4;      // scale
        const int blk = unit & 15;      // batch
        const int Wd[3] = {80, 40, 20};
        const int W = Wd[s], HW = W * W;

        // every warp redundantly computes prep for all 32 targets of batch blk
        // (one target per lane), entirely in registers.
        const float* tg = targets + (size_t)(blk * TT + lane) * 5;
        const float cls = tg[0], tx = tg[1], ty = tg[2], tw = tg[3], th = tg[4];

        int gx = (int)floorf(tx * (float)W); gx = min(max(gx, 0), W - 1);
        int gy = (int)floorf(ty * (float)W); gy = min(max(gy, 0), W - 1);

        float best = -1.f; int ba = 0;
        #pragma unroll
        for (int a = 0; a < 3; a++) {
            const float aw = c_anch[s * 6 + a * 2], ah = c_anch[s * 6 + a * 2 + 1];
            const float inter = fminf(tw, aw) * fminf(th, ah);
            const float iou = inter / (tw * th + aw * ah - inter + 1e-6f);
            if (iou > best) { best = iou; ba = a; }   // first-max wins
        }
        const int valid = (best > 0.3f) ? 1 : 0;
        const int lin = (gy * W + gx) * 3 + ba;

        const unsigned match = __match_any_sync(FULL, lin);
        const unsigned vmask = __ballot_sync(FULL, valid != 0);
        const unsigned later = 0xFFFFFFFEu << lane;
        const int ok_self = valid && !(match & vmask & later);

        const float aw = c_anch[s * 6 + ba * 2], ah = c_anch[s * 6 + ba * 2 + 1];
        const float tb0 = tx * (float)W - (float)gx;
        const float tb1 = ty * (float)W - (float)gy;
        const float tb2 = __logf(tw / aw + 1e-6f);
        const float tb3 = __logf(th / ah + 1e-6f);
        const int meta = (gy << 16) | (gx << 8) | (ba << 5) | (int)cls;

        const float* p = (s == 0) ? p0 : ((s == 1) ? p1 : p2);

        float bd = 0.f, os = 0.f, ns = 0.f, cs = 0.f, nv = 0.f;
        #pragma unroll
        for (int j = 0; j < 4; j++) {
            const int r = (w << 2) + j;    // target index 0..31 (8 warps x 4)
            const int okr  = __shfl_sync(FULL, ok_self, r);
            const int m    = __shfl_sync(FULL, meta, r);
            const float b0 = __shfl_sync(FULL, tb0, r);
            const float b1 = __shfl_sync(FULL, tb1, r);
            const float b2 = __shfl_sync(FULL, tb2, r);
            const float b3 = __shfl_sync(FULL, tb3, r);
            if (okr) {
                nv += (lane == 0) ? 1.f : 0.f;
                const int rgy = m >> 16, rgx = (m >> 8) & 0xff;
                const int rba = (m >> 5) & 3, rcls = m & 31;
                if (lane < 25) {
                    const float x = p[(size_t)(blk * 75 + rba * 25 + lane) * HW
                                      + rgy * W + rgx];
                    if (lane < 4) {
                        const float tb = (lane == 0) ? b0 :
                                         (lane == 1) ? b1 :
                                         (lane == 2) ? b2 : b3;
                        bd += tb * tb - 2.f * x * tb;
                    } else if (lane == 4) {
                        os += sp(-x);
                        ns += sp(x);
                    } else {
                        float c = sp(x);
                        if (lane - 5 == rcls) c -= x;
                        cs += c;
                    }
                }
            }
        }
        bd = warp_sum(bd); os = warp_sum(os); ns = warp_sum(ns);
        cs = warp_sum(cs); nv = warp_sum(nv);
        if (lane == 0) {
            atomicAdd(&g_acc[s][2], bd);
            atomicAdd(&g_acc[s][3], os);
            atomicAdd(&g_acc[s][4], ns);
            atomicAdd(&g_acc[s][5], cs);
            atomicAdd(&g_acc[s][6], nv);
        }
    }

    // ---------------- last-block finalize (shortened serial tail) ----------
    __shared__ int is_last;
    __syncthreads();                 // all block atomics issued (happens-before)
    if (tid == 0) {
        __threadfence();             // cumulative: orders the block's RED/ATOMs
        is_last = (atomicAdd(&g_ticket, 1) == NBLK - 1);
    }
    __syncthreads();
    if (!is_last) return;

    // warp 0: one parallel L2 round-trip for all 21 accumulators
    if (w == 0) {
        __shared__ float tot[21];
        if (lane < 21) tot[lane] = (&g_acc[0][0])[lane];
        __syncwarp();
        if (lane == 0) {
            const int Wd[3] = {80, 40, 20};
            float total = 0.f;
            #pragma unroll
            for (int sc = 0; sc < 3; sc++) {
                const float bb   = tot[sc * 7 + 0];
                const float ss   = tot[sc * 7 + 1];
                const float bdq  = tot[sc * 7 + 2];
                const float osum = tot[sc * 7 + 3];
                const float nsub = tot[sc * 7 + 4];
                const float csum = tot[sc * 7 + 5];
                const float nobj = tot[sc * 7 + 6];
                const float cells = (float)(BB * Wd[sc] * Wd[sc] * 3);
                const float n_obj = nobj + 1e-6f;
                const float n_noobj = (cells - nobj) + 1e-6f;
                const float box_loss   = (bb + bdq) / n_obj;
                const float obj_loss   = osum / n_obj;
                const float noobj_loss = (ss - nsub) / n_noobj;
                const float cls_loss   = csum / n_obj;
                total += 0.05f * box_loss
                       + 1.5f * (obj_loss + 0.5f * noobj_loss)
                       + 0.15f * cls_loss;
            }
            out[0] = total;
        }
        // parallel reset for the next graph replay
        if (lane < 21) (&g_acc[0][0])[lane] = 0.f;
        if (lane == 0) g_ticket = 0;
    }
}

extern "C" void kernel_launch(void* const* d_in, const int* in_sizes, int n_in,
                              void* d_out, int out_size) {
    const float* p0 = (const float*)d_in[0];
    const float* p1 = (const float*)d_in[1];
    const float* p2 = (const float*)d_in[2];
    const float* tg = (const float*)d_in[3];
    float* out = (float*)d_out;

    fused_kernel<<<NBLK, 256>>>(p0, p1, p2, tg, out);
}

// round 16
// speedup vs baseline: 1.0299x; 1.0299x over previous
#include <cuda_runtime.h>
#include <math.h>

#define BB 16
#define TT 32

__constant__ float c_anch[18] = {
    10.f/8.f, 13.f/8.f, 16.f/8.f, 30.f/8.f, 33.f/8.f, 23.f/8.f,
    30.f/16.f, 61.f/16.f, 62.f/16.f, 45.f/16.f, 59.f/16.f, 119.f/16.f,
    116.f/32.f, 90.f/32.f, 156.f/32.f, 198.f/32.f, 373.f/32.f, 326.f/32.f
};

// Dense geometry (runs of 5 contiguous channels per (b,anchor), run = b*3+a).
// 256-thread blocks, 8 front-batched float4 loads per thread (2048 f4/block)
// — the measured MLP optimum (delivery GB/s: 2->843, 4->927, 8->1011, 16->972):
//   scale0: 48 runs x 8000 f4, 4 blocks/run -> dense idx [0,192)
//   scale1: 48 runs x 2000 f4, 1 block/run  -> dense idx [192,240)
//   scale2: 48 runs x  500 f4, 4 runs/block -> dense idx [240,252)
// Corr: 48 DEDICATED blocks [252,300) — dispatched AFTER the dense stream
// (measured faster than corr-first or corr-fused-into-dense-blocks).
// One (scale,batch) unit each, 8 warps x 4 targets, warp-local register
// prep + __match_any shadow detection + shuffle gather.
#define NDB 252
#define NCB 48
#define NBLK (NDB + NCB)   // 300 blocks x 256 threads

// accumulators per scale: [0]=box_base [1]=sp_base [2]=box_delta
//                         [3]=obj_sum [4]=noobj_sub [5]=cls_sum [6]=n_obj
// zero at init; reset by the last block of every replay.
__device__ float g_acc[3][7];
__device__ int   g_ticket;

__device__ __forceinline__ float sp(float x) {
    // softplus = max(x,0) + log1p(exp(-|x|)); 2-MUFU form
    const float z = exp2f(-1.44269504f * fabsf(x));
    return fmaxf(x, 0.f) + 0.69314718f * __log2f(1.f + z);
}

__device__ __forceinline__ float warp_sum(float v) {
    #pragma unroll
    for (int o = 16; o; o >>= 1) v += __shfl_down_sync(0xffffffffu, v, o);
    return v;
}

__global__ void __launch_bounds__(256)
fused_kernel(const float* __restrict__ p0,
             const float* __restrict__ p1,
             const float* __restrict__ p2,
             const float* __restrict__ targets,
             float* __restrict__ out) {
    const int bid = blockIdx.x, tid = threadIdx.x;
    const int lane = tid & 31, w = tid >> 5;
    const unsigned FULL = 0xffffffffu;

    __shared__ float red[8][2];

    if (bid < NDB) {
        // ================= dense block: 8 front-batched LDG.128 =============
        float4 v[8];
        bool isbox[8];
        const float4 z4 = make_float4(0.f, 0.f, 0.f, 0.f);
        int dsc;

        if (bid < 192) {
            dsc = 0;
            const int run = bid >> 2, q = bid & 3;
            const float4* b4 = reinterpret_cast<const float4*>(p0) + run * 40000;
            const int f0 = q * 2048;
            #pragma unroll
            for (int k = 0; k < 8; k++) {
                const int i = f0 + k * 256 + tid;
                const bool ok = i < 8000;
                v[k] = ok ? b4[i] : z4;
                isbox[k] = (!ok) || (i < 6400);
            }
        } else if (bid < 240) {
            dsc = 1;
            const int run = bid - 192;
            const float4* b4 = reinterpret_cast<const float4*>(p1) + run * 10000;
            #pragma unroll
            for (int k = 0; k < 8; k++) {
                const int i = k * 256 + tid;
                const bool ok = i < 2000;
                v[k] = ok ? b4[i] : z4;
                isbox[k] = (!ok) || (i < 1600);
            }
        } else {
            dsc = 2;
            const int j = bid - 240;                   // 4 runs per block
            const float4* b4 = reinterpret_cast<const float4*>(p2) + j * 10000;
            #pragma unroll
            for (int k = 0; k < 8; k++) {
                const int i = k * 256 + tid;
                const bool ok = i < 2000;
                const int r = i / 500;                 // constant divisor
                const int off = i - 500 * r;
                v[k] = ok ? b4[r * 2500 + off] : z4;
                isbox[k] = (!ok) || (off < 400);
            }
        }

        float bacc = 0.f, sacc = 0.f;
        #pragma unroll
        for (int k = 0; k < 8; k++) {
            if (isbox[k]) {
                bacc += v[k].x * v[k].x + v[k].y * v[k].y
                      + v[k].z * v[k].z + v[k].w * v[k].w;
            } else {
                sacc += sp(v[k].x) + sp(v[k].y) + sp(v[k].z) + sp(v[k].w);
            }
        }
        bacc = warp_sum(bacc); sacc = warp_sum(sacc);
        if (lane == 0) { red[w][0] = bacc; red[w][1] = sacc; }
        __syncthreads();
        if (tid == 0) {
            float b2 = 0.f, s2 = 0.f;
            #pragma unroll
            for (int i = 0; i < 8; i++) { b2 += red[i][0]; s2 += red[i][1]; }
            atomicAdd(&g_acc[dsc][0], b2);
            atomicAdd(&g_acc[dsc][1], s2);
        }
    } else {
        // ================= dedicated corr block (no dense work) =============
        const int unit = bid - NDB;     // 0..47
        const int s   = unit >> 4;      // scale
        const int blk = unit & 15;      // batch
        const int Wd[3] = {80, 40, 20};
        const int W = Wd[s], HW = W * W;

        // every warp redundantly computes prep for all 32 targets of batch blk
        // (one target per lane), entirely in registers.
        const float* tg = targets + (size_t)(blk * TT + lane) * 5;
        const float cls = tg[0], tx = tg[1], ty = tg[2], tw = tg[3], th = tg[4];

        int gx = (int)floorf(tx * (float)W); gx = min(max(gx, 0), W - 1);
        int gy = (int)floorf(ty * (float)W); gy = min(max(gy, 0), W - 1);

        float best = -1.f; int ba = 0;
        #pragma unroll
        for (int a = 0; a < 3; a++) {
            const float aw = c_anch[s * 6 + a * 2], ah = c_anch[s * 6 + a * 2 + 1];
            const float inter = fminf(tw, aw) * fminf(th, ah);
            const float iou = inter / (tw * th + aw * ah - inter + 1e-6f);
            if (iou > best) { best = iou; ba = a; }   // first-max wins
        }
        const int valid = (best > 0.3f) ? 1 : 0;
        const int lin = (gy * W + gx) * 3 + ba;

        const unsigned match = __match_any_sync(FULL, lin);
        const unsigned vmask = __ballot_sync(FULL, valid != 0);
        const unsigned later = 0xFFFFFFFEu << lane;
        const int ok_self = valid && !(match & vmask & later);

        const float aw = c_anch[s * 6 + ba * 2], ah = c_anch[s * 6 + ba * 2 + 1];
        const float tb0 = tx * (float)W - (float)gx;
        const float tb1 = ty * (float)W - (float)gy;
        const float tb2 = __logf(tw / aw + 1e-6f);
        const float tb3 = __logf(th / ah + 1e-6f);
        const int meta = (gy << 16) | (gx << 8) | (ba << 5) | (int)cls;

        const float* p = (s == 0) ? p0 : ((s == 1) ? p1 : p2);

        float bd = 0.f, os = 0.f, ns = 0.f, cs = 0.f, nv = 0.f;
        #pragma unroll
        for (int j = 0; j < 4; j++) {
            const int r = (w << 2) + j;    // target index 0..31 (8 warps x 4)
            const int okr  = __shfl_sync(FULL, ok_self, r);
            const int m    = __shfl_sync(FULL, meta, r);
            const float b0 = __shfl_sync(FULL, tb0, r);
            const float b1 = __shfl_sync(FULL, tb1, r);
            const float b2 = __shfl_sync(FULL, tb2, r);
            const float b3 = __shfl_sync(FULL, tb3, r);
            if (okr) {
                nv += (lane == 0) ? 1.f : 0.f;
                const int rgy = m >> 16, rgx = (m >> 8) & 0xff;
                const int rba = (m >> 5) & 3, rcls = m & 31;
                if (lane < 25) {
                    const float x = p[(size_t)(blk * 75 + rba * 25 + lane) * HW
                                      + rgy * W + rgx];
                    if (lane < 4) {
                        const float tb = (lane == 0) ? b0 :
                                         (lane == 1) ? b1 :
                                         (lane == 2) ? b2 : b3;
                        bd += tb * tb - 2.f * x * tb;
                    } else if (lane == 4) {
                        os += sp(-x);
                        ns += sp(x);
                    } else {
                        float c = sp(x);
                        if (lane - 5 == rcls) c -= x;
                        cs += c;
                    }
                }
            }
        }
        bd = warp_sum(bd); os = warp_sum(os); ns = warp_sum(ns);
        cs = warp_sum(cs); nv = warp_sum(nv);
        if (lane == 0) {
            atomicAdd(&g_acc[s][2], bd);
            atomicAdd(&g_acc[s][3], os);
            atomicAdd(&g_acc[s][4], ns);
            atomicAdd(&g_acc[s][5], cs);
            atomicAdd(&g_acc[s][6], nv);
        }
    }

    // ---------------- last-block finalize ----------------
    __threadfence();
    __shared__ int is_last;
    __syncthreads();
    if (tid == 0) is_last = (atomicAdd(&g_ticket, 1) == NBLK - 1);
    __syncthreads();
    if (!is_last) return;

    if (tid == 0) {
        const int Wd[3] = {80, 40, 20};
        float total = 0.f;
        #pragma unroll
        for (int sc = 0; sc < 3; sc++) {
            const float bb   = g_acc[sc][0];
            const float ss   = g_acc[sc][1];
            const float bdq  = g_acc[sc][2];
            const float osum = g_acc[sc][3];
            const float nsub = g_acc[sc][4];
            const float csum = g_acc[sc][5];
            const float nobj = g_acc[sc][6];
            const float cells = (float)(BB * Wd[sc] * Wd[sc] * 3);
            const float n_obj = nobj + 1e-6f;
            const float n_noobj = (cells - nobj) + 1e-6f;
            const float box_loss   = (bb + bdq) / n_obj;
            const float obj_loss   = osum / n_obj;
            const float noobj_loss = (ss - nsub) / n_noobj;
            const float cls_loss   = csum / n_obj;
            total += 0.05f * box_loss + 1.5f * (obj_loss + 0.5f * noobj_loss)
                   + 0.15f * cls_loss;
        }
        out[0] = total;
        // reset accumulators for the next graph replay
        #pragma unroll
        for (int sc = 0; sc < 3; sc++)
            #pragma unroll
            for (int q = 0; q < 7; q++) g_acc[sc][q] = 0.f;
        g_ticket = 0;
    }
}

extern "C" void kernel_launch(void* const* d_in, const int* in_sizes, int n_in,
                              void* d_out, int out_size) {
    const float* p0 = (const float*)d_in[0];
    const float* p1 = (const float*)d_in[1];
    const float* p2 = (const float*)d_in[2];
    const float* tg = (const float*)d_in[3];
    float* out = (float*)d_out;

    fused_kernel<<<NBLK, 256>>>(p0, p1, p2, tg, out);
}